// round 10
// baseline (speedup 1.0000x reference)
#include <cuda_runtime.h>
#include <stdint.h>

// out[e,f] = (node_src[src[e],f] + off_src[e,f]) * (node_tgt[tgt[e],f] + off_tgt[e,f])
// F = 256 floats, E = 300000, N = 50000, edge_ids int32. HBM-bound.
//
// R10: R5 structure (8 floats/thread, 32B evict-last node gathers), but the
// zero-reuse streams use the strongest no-cache ops:
//   - off_src / off_tgt reads:  ld.global.cv  (volatile, don't cache)
//   - out writes:               st.global.wt  (write-through)
// Goal: streams stop allocating/displacing in L2 -> node tables (102 MB) own
// the ~126 MB L2 -> gather hit rate 51% -> ~83% (compulsory only), while the
// edge-row access order stays fully contiguous (no DRAM row fragmentation).

#define FEAT8 32  // 256 / 8

struct F8 { float4 lo, hi; };

__device__ __forceinline__ F8 ldg_evict_last_32B(const void* p) {
    unsigned long long r0, r1, r2, r3;
    asm volatile("ld.global.nc.L2::evict_last.v4.b64 {%0,%1,%2,%3}, [%4];"
                 : "=l"(r0), "=l"(r1), "=l"(r2), "=l"(r3)
                 : "l"(p));
    F8 v;
    v.lo.x = __uint_as_float((unsigned)(r0));
    v.lo.y = __uint_as_float((unsigned)(r0 >> 32));
    v.lo.z = __uint_as_float((unsigned)(r1));
    v.lo.w = __uint_as_float((unsigned)(r1 >> 32));
    v.hi.x = __uint_as_float((unsigned)(r2));
    v.hi.y = __uint_as_float((unsigned)(r2 >> 32));
    v.hi.z = __uint_as_float((unsigned)(r3));
    v.hi.w = __uint_as_float((unsigned)(r3 >> 32));
    return v;
}

__global__ __launch_bounds__(256) void node_to_edge_kernel(
    const float* __restrict__ node_src,    // [N, 256]
    const float* __restrict__ node_tgt,    // [N, 256]
    const int* __restrict__ edge_src_ids,  // [E]
    const int* __restrict__ edge_tgt_ids,  // [E]
    const float4* __restrict__ off_src,    // [E, 64] as float4
    const float4* __restrict__ off_tgt,    // [E, 64]
    float4* __restrict__ out,              // [E, 64]
    long long total8)                      // E * 32
{
    long long idx = (long long)blockIdx.x * blockDim.x + threadIdx.x;
    if (idx >= total8) return;

    long long e  = idx >> 5;        // idx / 32
    int       f8 = (int)(idx & 31); // 8-float group within row

    long long s = (long long)edge_src_ids[e];
    long long t = (long long)edge_tgt_ids[e];

    // Gathered node rows: 32B loads, pinned-ish in L2 (evict-last).
    F8 a = ldg_evict_last_32B(node_src + s * 256 + f8 * 8);
    F8 c = ldg_evict_last_32B(node_tgt + t * 256 + f8 * 8);

    // Single-use streams: volatile loads -> don't cache anywhere.
    long long q = idx * 2;  // float4 index
    float4 b0 = __ldcv(&off_src[q]);
    float4 b1 = __ldcv(&off_src[q + 1]);
    float4 d0 = __ldcv(&off_tgt[q]);
    float4 d1 = __ldcv(&off_tgt[q + 1]);

    float4 r0, r1;
    r0.x = (a.lo.x + b0.x) * (c.lo.x + d0.x);
    r0.y = (a.lo.y + b0.y) * (c.lo.y + d0.y);
    r0.z = (a.lo.z + b0.z) * (c.lo.z + d0.z);
    r0.w = (a.lo.w + b0.w) * (c.lo.w + d0.w);
    r1.x = (a.hi.x + b1.x) * (c.hi.x + d1.x);
    r1.y = (a.hi.y + b1.y) * (c.hi.y + d1.y);
    r1.z = (a.hi.z + b1.z) * (c.hi.z + d1.z);
    r1.w = (a.hi.w + b1.w) * (c.hi.w + d1.w);

    // Output: write-through, don't retain in L2.
    __stwt(&out[q], r0);
    __stwt(&out[q + 1], r1);
}

extern "C" void kernel_launch(void* const* d_in, const int* in_sizes, int n_in,
                              void* d_out, int out_size) {
    // 0: node_src_feats [N,256] f32   1: node_tgt_feats [N,256] f32
    // 2: edge_ids [2,E] int32         3: off_edge_src [E,256] f32
    // 4: off_edge_tgt [E,256] f32
    const float*  node_src = (const float*)d_in[0];
    const float*  node_tgt = (const float*)d_in[1];
    const int*    edge_ids = (const int*)d_in[2];
    const float4* off_src  = (const float4*)d_in[3];
    const float4* off_tgt  = (const float4*)d_in[4];
    float4*       out      = (float4*)d_out;

    long long E = (long long)in_sizes[2] / 2;        // edge_ids has 2*E elems
    long long total8 = E * FEAT8;                    // 8-float groups of output

    const int* src_ids = edge_ids;                   // row 0
    const int* tgt_ids = edge_ids + E;               // row 1

    int threads = 256;
    long long blocks = (total8 + threads - 1) / threads;
    node_to_edge_kernel<<<(unsigned)blocks, threads>>>(
        node_src, node_tgt, src_ids, tgt_ids, off_src, off_tgt, out, total8);
}

// round 11
// speedup vs baseline: 1.0827x; 1.0827x over previous
#include <cuda_runtime.h>
#include <stdint.h>

// out[e,f] = (node_src[src[e],f] + off_src[e,f]) * (node_tgt[tgt[e],f] + off_tgt[e,f])
// F = 256 floats, E = 300000, N = 50000, edge_ids int32. HBM-bound.
//
// Final form (R5 consolidated): 8 floats/thread; one warp covers one full
// 1 KB edge row (contiguous streams, full-line gathers).
//   - node gathers: 256-bit ld.global.nc.L2::evict_last (32 B/thread/table)
//   - streams (off_src/off_tgt/out): .cs evict-first, 128-bit
//   - stream loads issued FIRST (DRAM-bound) so gather L2 hits overlap them
//   - 32-bit unsigned indexing (all byte offsets < 2^31)
// Measured operating point: ~1.22 GB DRAM traffic at ~7.1 TB/s (~89% of peak).

#define FEAT8 32  // 256 / 8

struct F8 { float4 lo, hi; };

__device__ __forceinline__ F8 ldg_evict_last_32B(const void* p) {
    unsigned long long r0, r1, r2, r3;
    asm volatile("ld.global.nc.L2::evict_last.v4.b64 {%0,%1,%2,%3}, [%4];"
                 : "=l"(r0), "=l"(r1), "=l"(r2), "=l"(r3)
                 : "l"(p));
    F8 v;
    v.lo.x = __uint_as_float((unsigned)(r0));
    v.lo.y = __uint_as_float((unsigned)(r0 >> 32));
    v.lo.z = __uint_as_float((unsigned)(r1));
    v.lo.w = __uint_as_float((unsigned)(r1 >> 32));
    v.hi.x = __uint_as_float((unsigned)(r2));
    v.hi.y = __uint_as_float((unsigned)(r2 >> 32));
    v.hi.z = __uint_as_float((unsigned)(r3));
    v.hi.w = __uint_as_float((unsigned)(r3 >> 32));
    return v;
}

__global__ __launch_bounds__(256) void node_to_edge_kernel(
    const float* __restrict__ node_src,    // [N, 256]
    const float* __restrict__ node_tgt,    // [N, 256]
    const int* __restrict__ edge_src_ids,  // [E]
    const int* __restrict__ edge_tgt_ids,  // [E]
    const float4* __restrict__ off_src,    // [E, 64] as float4
    const float4* __restrict__ off_tgt,    // [E, 64]
    float4* __restrict__ out,              // [E, 64]
    unsigned total8)                       // E * 32
{
    unsigned idx = blockIdx.x * blockDim.x + threadIdx.x;
    if (idx >= total8) return;

    unsigned e  = idx >> 5;        // edge id
    unsigned f8 = idx & 31;        // 8-float group within row

    // Start the single-use stream loads first (these are the DRAM-latency
    // critical path); .cs so they insert evict-first in L2.
    unsigned q = idx * 2;          // float4 index (< 2^27, safe)
    float4 b0 = __ldcs(&off_src[q]);
    float4 b1 = __ldcs(&off_src[q + 1]);
    float4 d0 = __ldcs(&off_tgt[q]);
    float4 d1 = __ldcs(&off_tgt[q + 1]);

    unsigned s = (unsigned)__ldg(&edge_src_ids[e]);
    unsigned t = (unsigned)__ldg(&edge_tgt_ids[e]);

    // Gathered node rows: 32 B, kept L2-resident (evict-last hint).
    F8 a = ldg_evict_last_32B(node_src + (size_t)s * 256 + f8 * 8);
    F8 c = ldg_evict_last_32B(node_tgt + (size_t)t * 256 + f8 * 8);

    float4 r0, r1;
    r0.x = (a.lo.x + b0.x) * (c.lo.x + d0.x);
    r0.y = (a.lo.y + b0.y) * (c.lo.y + d0.y);
    r0.z = (a.lo.z + b0.z) * (c.lo.z + d0.z);
    r0.w = (a.lo.w + b0.w) * (c.lo.w + d0.w);
    r1.x = (a.hi.x + b1.x) * (c.hi.x + d1.x);
    r1.y = (a.hi.y + b1.y) * (c.hi.y + d1.y);
    r1.z = (a.hi.z + b1.z) * (c.hi.z + d1.z);
    r1.w = (a.hi.w + b1.w) * (c.hi.w + d1.w);

    __stcs(&out[q], r0);
    __stcs(&out[q + 1], r1);
}

extern "C" void kernel_launch(void* const* d_in, const int* in_sizes, int n_in,
                              void* d_out, int out_size) {
    // 0: node_src_feats [N,256] f32   1: node_tgt_feats [N,256] f32
    // 2: edge_ids [2,E] int32         3: off_edge_src [E,256] f32
    // 4: off_edge_tgt [E,256] f32
    const float*  node_src = (const float*)d_in[0];
    const float*  node_tgt = (const float*)d_in[1];
    const int*    edge_ids = (const int*)d_in[2];
    const float4* off_src  = (const float4*)d_in[3];
    const float4* off_tgt  = (const float4*)d_in[4];
    float4*       out      = (float4*)d_out;

    unsigned E = (unsigned)(in_sizes[2] / 2);        // edge_ids has 2*E elems
    unsigned total8 = E * FEAT8;                     // 8-float groups of output

    const int* src_ids = edge_ids;                   // row 0
    const int* tgt_ids = edge_ids + E;               // row 1

    unsigned threads = 256;
    unsigned blocks = (total8 + threads - 1) / threads;
    node_to_edge_kernel<<<blocks, threads>>>(
        node_src, node_tgt, src_ids, tgt_ids, off_src, off_tgt, out, total8);
}

// round 12
// speedup vs baseline: 1.0873x; 1.0042x over previous
#include <cuda_runtime.h>
#include <stdint.h>

// out[e,f] = (node_src[src[e],f] + off_src[e,f]) * (node_tgt[tgt[e],f] + off_tgt[e,f])
// F = 256 floats, E = 300000, N = 50000, edge_ids int32. HBM-bound.
//
// R12: asymmetric L2 pinning test. Hypothesis: the evict_last pool is
// capacity-capped, so pinning BOTH tables (102 MB, R5/R11) oversubscribes it
// and degrades to no-op. Pin ONLY the src table (51.2 MB) evict_last; tgt
// uses default policy; streams (off_src/off_tgt/out) stay .cs evict-first.
// If the pool holds, src gather DRAM drops to ~51 MB compulsory.

#define FEAT8 32  // 256 / 8

struct F8 { float4 lo, hi; };

__device__ __forceinline__ F8 ldg_evict_last_32B(const void* p) {
    unsigned long long r0, r1, r2, r3;
    asm volatile("ld.global.nc.L2::evict_last.v4.b64 {%0,%1,%2,%3}, [%4];"
                 : "=l"(r0), "=l"(r1), "=l"(r2), "=l"(r3)
                 : "l"(p));
    F8 v;
    v.lo.x = __uint_as_float((unsigned)(r0));
    v.lo.y = __uint_as_float((unsigned)(r0 >> 32));
    v.lo.z = __uint_as_float((unsigned)(r1));
    v.lo.w = __uint_as_float((unsigned)(r1 >> 32));
    v.hi.x = __uint_as_float((unsigned)(r2));
    v.hi.y = __uint_as_float((unsigned)(r2 >> 32));
    v.hi.z = __uint_as_float((unsigned)(r3));
    v.hi.w = __uint_as_float((unsigned)(r3 >> 32));
    return v;
}

__device__ __forceinline__ F8 ldg_default_32B(const float* p) {
    const float4* p4 = (const float4*)p;
    F8 v;
    v.lo = __ldg(p4);
    v.hi = __ldg(p4 + 1);
    return v;
}

__global__ __launch_bounds__(256) void node_to_edge_kernel(
    const float* __restrict__ node_src,    // [N, 256]
    const float* __restrict__ node_tgt,    // [N, 256]
    const int* __restrict__ edge_src_ids,  // [E]
    const int* __restrict__ edge_tgt_ids,  // [E]
    const float4* __restrict__ off_src,    // [E, 64] as float4
    const float4* __restrict__ off_tgt,    // [E, 64]
    float4* __restrict__ out,              // [E, 64]
    unsigned total8)                       // E * 32
{
    unsigned idx = blockIdx.x * blockDim.x + threadIdx.x;
    if (idx >= total8) return;

    unsigned e  = idx >> 5;        // edge id
    unsigned f8 = idx & 31;        // 8-float group within row

    // Single-use streams first (DRAM-latency critical path), evict-first.
    unsigned q = idx * 2;          // float4 index
    float4 b0 = __ldcs(&off_src[q]);
    float4 b1 = __ldcs(&off_src[q + 1]);
    float4 d0 = __ldcs(&off_tgt[q]);
    float4 d1 = __ldcs(&off_tgt[q + 1]);

    unsigned s = (unsigned)__ldg(&edge_src_ids[e]);
    unsigned t = (unsigned)__ldg(&edge_tgt_ids[e]);

    // src table: evict_last (51.2 MB — fits a capped pin pool).
    F8 a = ldg_evict_last_32B(node_src + (size_t)s * 256 + f8 * 8);
    // tgt table: default policy.
    F8 c = ldg_default_32B(node_tgt + (size_t)t * 256 + f8 * 8);

    float4 r0, r1;
    r0.x = (a.lo.x + b0.x) * (c.lo.x + d0.x);
    r0.y = (a.lo.y + b0.y) * (c.lo.y + d0.y);
    r0.z = (a.lo.z + b0.z) * (c.lo.z + d0.z);
    r0.w = (a.lo.w + b0.w) * (c.lo.w + d0.w);
    r1.x = (a.hi.x + b1.x) * (c.hi.x + d1.x);
    r1.y = (a.hi.y + b1.y) * (c.hi.y + d1.y);
    r1.z = (a.hi.z + b1.z) * (c.hi.z + d1.z);
    r1.w = (a.hi.w + b1.w) * (c.hi.w + d1.w);

    __stcs(&out[q], r0);
    __stcs(&out[q + 1], r1);
}

extern "C" void kernel_launch(void* const* d_in, const int* in_sizes, int n_in,
                              void* d_out, int out_size) {
    // 0: node_src_feats [N,256] f32   1: node_tgt_feats [N,256] f32
    // 2: edge_ids [2,E] int32         3: off_edge_src [E,256] f32
    // 4: off_edge_tgt [E,256] f32
    const float*  node_src = (const float*)d_in[0];
    const float*  node_tgt = (const float*)d_in[1];
    const int*    edge_ids = (const int*)d_in[2];
    const float4* off_src  = (const float4*)d_in[3];
    const float4* off_tgt  = (const float4*)d_in[4];
    float4*       out      = (float4*)d_out;

    unsigned E = (unsigned)(in_sizes[2] / 2);        // edge_ids has 2*E elems
    unsigned total8 = E * FEAT8;                     // 8-float groups of output

    const int* src_ids = edge_ids;                   // row 0
    const int* tgt_ids = edge_ids + E;               // row 1

    unsigned threads = 256;
    unsigned blocks = (total8 + threads - 1) / threads;
    node_to_edge_kernel<<<blocks, threads>>>(
        node_src, node_tgt, src_ids, tgt_ids, off_src, off_tgt, out, total8);
}